// round 7
// baseline (speedup 1.0000x reference)
#include <cuda_runtime.h>
#include <cuda_fp16.h>
#include <math.h>
#include <stdint.h>

#define K_DIM 4096
#define C_DIM 2048
#define B_DIM 8192

// ---------------------------------------------------------------------------
// Device scratch (no allocation allowed)
// ---------------------------------------------------------------------------
__device__ float g_partial[1024];
__device__ float g_coef[2];   // {k1 = 8192*256*alpha, k2 = 32*(-32640)*alpha^2}

__device__ __half g_AhT[(size_t)C_DIM * K_DIM];  // fp16(64*A^T)  (C x K)
__device__ __half g_AlT[(size_t)C_DIM * K_DIM];  // fp16 residual
__device__ __half g_qh[(size_t)B_DIM * C_DIM];   // fp16(q)
__device__ float  g_G [(size_t)C_DIM * C_DIM];   // G = A^T A (fp32)
__device__ __half g_Gh[(size_t)C_DIM * C_DIM];   // fp16(16*G)
__device__ __half g_Ph[(size_t)C_DIM * C_DIM];   // fp16(8192*P)

// ---------------------------------------------------------------------------
// Helpers (baseline sm_103 PTX only: cp.async + ldmatrix + mma.sync)
// ---------------------------------------------------------------------------
__device__ __forceinline__ uint32_t smem_to_u32(const void* smem_ptr) {
    uint32_t addr;
    asm("{ .reg .u64 tmp; cvta.to.shared.u64 tmp, %1; cvt.u32.u64 %0, tmp; }"
        : "=r"(addr) : "l"(smem_ptr));
    return addr;
}

__device__ __forceinline__ void cp_async16(uint32_t dst, const void* src) {
    asm volatile("cp.async.cg.shared.global [%0], [%1], 16;"
                 :: "r"(dst), "l"(src));
}
#define CP_COMMIT() asm volatile("cp.async.commit_group;" ::: "memory")
#define CP_WAIT1()  asm volatile("cp.async.wait_group 1;" ::: "memory")
#define CP_WAIT2()  asm volatile("cp.async.wait_group 2;" ::: "memory")
#define CP_WAIT0()  asm volatile("cp.async.wait_group 0;" ::: "memory")

__device__ __forceinline__ void ldsm_x4(uint32_t& r0, uint32_t& r1,
                                        uint32_t& r2, uint32_t& r3,
                                        uint32_t addr) {
    asm volatile("ldmatrix.sync.aligned.m8n8.x4.shared.b16 {%0,%1,%2,%3}, [%4];"
                 : "=r"(r0), "=r"(r1), "=r"(r2), "=r"(r3) : "r"(addr));
}

__device__ __forceinline__ void mma16816(float* c, const uint32_t* a,
                                         const uint32_t* b) {
    asm volatile(
        "mma.sync.aligned.m16n8k16.row.col.f32.f16.f16.f32 "
        "{%0,%1,%2,%3}, {%4,%5,%6,%7}, {%8,%9}, {%0,%1,%2,%3};"
        : "+f"(c[0]), "+f"(c[1]), "+f"(c[2]), "+f"(c[3])
        : "r"(a[0]), "r"(a[1]), "r"(a[2]), "r"(a[3]), "r"(b[0]), "r"(b[1]));
}

__device__ __forceinline__ uint32_t pack_h2(float a, float b) {
    __half2 h = __floats2half2_rn(a, b);
    return *reinterpret_cast<uint32_t*>(&h);
}

// ---------------------------------------------------------------------------
// ||A||_F^2 + alpha
// ---------------------------------------------------------------------------
__global__ void fro_partial_kernel(const float* __restrict__ A, int n4) {
    const float4* A4 = (const float4*)A;
    float s = 0.f;
    for (int i = blockIdx.x * blockDim.x + threadIdx.x; i < n4;
         i += gridDim.x * blockDim.x) {
        float4 v = A4[i];
        s += v.x * v.x + v.y * v.y + v.z * v.z + v.w * v.w;
    }
    __shared__ float sh[256];
    int t = threadIdx.x;
    sh[t] = s;
    __syncthreads();
    for (int o = 128; o > 0; o >>= 1) {
        if (t < o) sh[t] += sh[t + o];
        __syncthreads();
    }
    if (t == 0) g_partial[blockIdx.x] = sh[0];
}

__global__ void finalize_alpha_kernel(const float* __restrict__ log_scale) {
    __shared__ float sh[1024];
    int t = threadIdx.x;
    sh[t] = g_partial[t];
    __syncthreads();
    for (int o = 512; o > 0; o >>= 1) {
        if (t < o) sh[t] += sh[t + o];
        __syncthreads();
    }
    if (t == 0) {
        float fro = sh[0];
        float a = fminf(expf(log_scale[0]), 5e-4f) / (fro + 1e-8f);
        g_coef[0] = 2097152.0f * a;          // 8192*256*alpha
        g_coef[1] = -1044480.0f * a * a;     // 32*(-32640)*alpha^2
    }
}

// ---------------------------------------------------------------------------
// Operand prep: A (K x C fp32) -> A^T hi/lo fp16 (scaled by 64), C x K
// ---------------------------------------------------------------------------
__global__ __launch_bounds__(256) void split_transpose_kernel(
    const float* __restrict__ A, __half* __restrict__ hiT,
    __half* __restrict__ loT) {
    __shared__ float tile[32][33];
    int tx = threadIdx.x & 31, ty = threadIdx.x >> 5;
    int c0 = blockIdx.x * 32;
    int k0 = blockIdx.y * 32;
#pragma unroll
    for (int i = 0; i < 4; i++) {
        int r = ty + i * 8;
        tile[r][tx] = A[(size_t)(k0 + r) * C_DIM + c0 + tx];
    }
    __syncthreads();
#pragma unroll
    for (int i = 0; i < 4; i++) {
        int p = ty + i * 8;
        float v = tile[tx][p] * 64.0f;
        size_t o = (size_t)(c0 + p) * K_DIM + k0 + tx;
        __half h = __float2half_rn(v);
        hiT[o] = h;
        loT[o] = __float2half_rn(v - __half2float(h));  // subnormal-safe
    }
}

// q -> fp16(q) only (single-term GEMM3; q rounding adds ~2.8e-4 RMS rel)
__global__ __launch_bounds__(256) void convert_kernel(
    const float* __restrict__ X, __half* __restrict__ hi, int n4) {
    const float4* X4 = (const float4*)X;
    uint2* H = (uint2*)hi;
    for (int i = blockIdx.x * blockDim.x + threadIdx.x; i < n4;
         i += gridDim.x * blockDim.x) {
        float4 v = X4[i];
        uint2 h;
        h.x = pack_h2(v.x, v.y);
        h.y = pack_h2(v.z, v.w);
        H[i] = h;
    }
}

// ---------------------------------------------------------------------------
// Unified mma.sync fp16 GEMM, K-major operands, acc fp32.
//   NT==3: acc = Ah.Bh^T + Al.Bh^T + Ah.Bl^T   (4 tiles/stage, 2 stages)
//   NT==1: acc = Ah.Bh^T                       (2 tiles/stage, 4 stages)
// CTA 128x128, 8 warps (2x4), warp tile 64x32, K-tile 32, ROWB=80 pad.
// EPI 0: Fout = s_f * acc
// EPI 1: Fout = acc/4096 (=G); Hout = fp16(acc/256) (=16G)    [+mirror if sym]
// EPI 2: Hout = fp16(k1*Gin + k2*acc)  (=8192*P)              [+mirror if sym]
// ---------------------------------------------------------------------------
#define KT 32
#define ROWB 80
#define TILE_BYTES (128 * ROWB)          // 10240
#define GEMM_SMEM 81920

template <int EPI, int NT>
__global__ void __launch_bounds__(256, 2) mma_gemm_kernel(
    const __half* __restrict__ Ah, const __half* __restrict__ Al,
    const __half* __restrict__ Bh, const __half* __restrict__ Bl,
    int K,
    const float* __restrict__ Gin, float* __restrict__ Fout,
    __half* __restrict__ Hout,
    int N, int sym, float s_f) {
    if (sym && (int)blockIdx.x > (int)blockIdx.y) return;

    extern __shared__ char smem[];
    const uint32_t smem_u = smem_to_u32(smem);
    const int tid = threadIdx.x;
    const int lane = tid & 31;
    const int warp = tid >> 5;
    const int wm = warp & 1;
    const int wn = warp >> 1;
    const int bm = blockIdx.y * 128;
    const int bn = blockIdx.x * 128;
    const int ktpt = K / KT;

    const int NSTG = (NT == 1) ? 4 : 2;
    const int STAGEB = (NT + 1) * TILE_BYTES;

    float acc[4][4][4];
#pragma unroll
    for (int mi = 0; mi < 4; mi++)
#pragma unroll
        for (int ni = 0; ni < 4; ni++)
#pragma unroll
            for (int c = 0; c < 4; c++) acc[mi][ni][c] = 0.f;

    const int cr = tid >> 2;       // row 0..63 (two passes -> 0..127)
    const int cc = tid & 3;        // 16B chunk

    auto issue = [&](int kt) {
        int k0 = kt * KT;
        uint32_t s = smem_u + (kt & (NSTG - 1)) * STAGEB;
#pragma unroll
        for (int i = 0; i < 2; i++) {
            int r = cr + i * 64;
            cp_async16(s + r * ROWB + cc * 16,
                       Ah + (size_t)(bm + r) * K + k0 + cc * 8);
        }
#pragma unroll
        for (int i = 0; i < 2; i++) {
            int r = cr + i * 64;
            cp_async16(s + TILE_BYTES + r * ROWB + cc * 16,
                       Bh + (size_t)(bn + r) * K + k0 + cc * 8);
        }
        if (NT == 3) {
#pragma unroll
            for (int i = 0; i < 2; i++) {
                int r = cr + i * 64;
                cp_async16(s + 2 * TILE_BYTES + r * ROWB + cc * 16,
                           Al + (size_t)(bm + r) * K + k0 + cc * 8);
            }
#pragma unroll
            for (int i = 0; i < 2; i++) {
                int r = cr + i * 64;
                cp_async16(s + 3 * TILE_BYTES + r * ROWB + cc * 16,
                           Bl + (size_t)(bn + r) * K + k0 + cc * 8);
            }
        }
        CP_COMMIT();
    };

    // prologue
    issue(0);
    issue(1);
    if (NT == 1) issue(2);

    // ldmatrix lane addressing
    const int arow = lane & 15;
    const int akb = (lane >> 4) * 16;
    const int brow = (lane & 7) + ((lane >> 4) << 3);
    const int bkb = ((lane >> 3) & 1) * 16;

    for (int kt = 0; kt < ktpt; kt++) {
        if (NT == 1) CP_WAIT2(); else CP_WAIT1();
        __syncthreads();
        uint32_t s0 = smem_u + (kt & (NSTG - 1)) * STAGEB;
#pragma unroll
        for (int ks = 0; ks < 2; ks++) {
            uint32_t a[4][4];
            uint32_t b[4][2];
#pragma unroll
            for (int mi = 0; mi < 4; mi++)
                ldsm_x4(a[mi][0], a[mi][1], a[mi][2], a[mi][3],
                        s0 + (uint32_t)(wm * 64 + mi * 16 + arow) * ROWB +
                            ks * 32 + akb);
#pragma unroll
            for (int nb = 0; nb < 2; nb++)
                ldsm_x4(b[2 * nb][0], b[2 * nb][1], b[2 * nb + 1][0],
                        b[2 * nb + 1][1],
                        s0 + TILE_BYTES +
                            (uint32_t)(wn * 32 + nb * 16 + brow) * ROWB +
                            ks * 32 + bkb);
#pragma unroll
            for (int mi = 0; mi < 4; mi++)
#pragma unroll
                for (int ni = 0; ni < 4; ni++)
                    mma16816(acc[mi][ni], a[mi], b[ni]);

            if (NT == 3) {
                // lh: Al x Bh
                uint32_t al[4][4];
#pragma unroll
                for (int mi = 0; mi < 4; mi++)
                    ldsm_x4(al[mi][0], al[mi][1], al[mi][2], al[mi][3],
                            s0 + 2 * TILE_BYTES +
                                (uint32_t)(wm * 64 + mi * 16 + arow) * ROWB +
                                ks * 32 + akb);
#pragma unroll
                for (int mi = 0; mi < 4; mi++)
#pragma unroll
                    for (int ni = 0; ni < 4; ni++)
                        mma16816(acc[mi][ni], al[mi], b[ni]);
                // hl: Ah x Bl
                uint32_t bl[4][2];
#pragma unroll
                for (int nb = 0; nb < 2; nb++)
                    ldsm_x4(bl[2 * nb][0], bl[2 * nb][1], bl[2 * nb + 1][0],
                            bl[2 * nb + 1][1],
                            s0 + 3 * TILE_BYTES +
                                (uint32_t)(wn * 32 + nb * 16 + brow) * ROWB +
                                ks * 32 + bkb);
#pragma unroll
                for (int mi = 0; mi < 4; mi++)
#pragma unroll
                    for (int ni = 0; ni < 4; ni++)
                        mma16816(acc[mi][ni], a[mi], bl[ni]);
            }
        }
        __syncthreads();
        int nx = kt + ((NT == 1) ? 3 : 2);
        if (nx < ktpt) issue(nx);
        else CP_COMMIT();   // keep group count invariant
    }
    CP_WAIT0();

    // ---------------- epilogue ----------------
    const int g = lane >> 2;
    const int tc = lane & 3;
    const int mirror = sym && ((int)blockIdx.x != (int)blockIdx.y);
    float k1 = 0.f, k2 = 0.f;
    if (EPI == 2) { k1 = g_coef[0]; k2 = g_coef[1]; }

#pragma unroll
    for (int mi = 0; mi < 4; mi++) {
#pragma unroll
        for (int ni = 0; ni < 4; ni++) {
#pragma unroll
            for (int half = 0; half < 2; half++) {
                int row = bm + wm * 64 + mi * 16 + g + half * 8;
                int col = bn + wn * 32 + ni * 8 + tc * 2;
                float a0 = acc[mi][ni][half * 2 + 0];
                float a1 = acc[mi][ni][half * 2 + 1];
                size_t off = (size_t)row * N + col;
                if (EPI == 0) {
                    *(float2*)(Fout + off) = make_float2(s_f * a0, s_f * a1);
                } else if (EPI == 1) {
                    float v0 = a0 * (1.0f / 4096.0f);
                    float v1 = a1 * (1.0f / 4096.0f);
                    *(float2*)(Fout + off) = make_float2(v0, v1);
                    uint32_t H = pack_h2(a0 * (1.0f / 256.0f),
                                         a1 * (1.0f / 256.0f));
                    *(uint32_t*)(Hout + off) = H;
                    if (mirror) {
                        Fout[(size_t)col * N + row] = v0;
                        Fout[(size_t)(col + 1) * N + row] = v1;
                        *(unsigned short*)(Hout + (size_t)col * N + row) =
                            (unsigned short)(H & 0xffff);
                        *(unsigned short*)(Hout + (size_t)(col + 1) * N + row) =
                            (unsigned short)(H >> 16);
                    }
                } else {  // EPI == 2
                    float2 gv = *(const float2*)(Gin + off);
                    float v0 = k1 * gv.x + k2 * a0;
                    float v1 = k1 * gv.y + k2 * a1;
                    uint32_t H = pack_h2(v0, v1);
                    *(uint32_t*)(Hout + off) = H;
                    if (mirror) {
                        *(unsigned short*)(Hout + (size_t)col * N + row) =
                            (unsigned short)(H & 0xffff);
                        *(unsigned short*)(Hout + (size_t)(col + 1) * N + row) =
                            (unsigned short)(H >> 16);
                    }
                }
            }
        }
    }
}

// ---------------------------------------------------------------------------
// Launch: retrieved = query @ (c1*G + c2*G^2), G = A^T A  (G, P symmetric)
// ---------------------------------------------------------------------------
extern "C" void kernel_launch(void* const* d_in, const int* in_sizes, int n_in,
                              void* d_out, int out_size) {
    const float* query = (const float*)d_in[0];      // (B, C)
    const float* A = (const float*)d_in[1];          // (K, C)
    const float* log_scale = (const float*)d_in[2];  // scalar
    float* out = (float*)d_out;                      // (B, C)

    __half *AhT, *AlT, *qh, *Gh, *Ph;
    float* G;
    cudaGetSymbolAddress((void**)&AhT, g_AhT);
    cudaGetSymbolAddress((void**)&AlT, g_AlT);
    cudaGetSymbolAddress((void**)&qh, g_qh);
    cudaGetSymbolAddress((void**)&G, g_G);
    cudaGetSymbolAddress((void**)&Gh, g_Gh);
    cudaGetSymbolAddress((void**)&Ph, g_Ph);

    cudaFuncSetAttribute(mma_gemm_kernel<0, 1>,
                         cudaFuncAttributeMaxDynamicSharedMemorySize, GEMM_SMEM);
    cudaFuncSetAttribute(mma_gemm_kernel<1, 3>,
                         cudaFuncAttributeMaxDynamicSharedMemorySize, GEMM_SMEM);
    cudaFuncSetAttribute(mma_gemm_kernel<2, 1>,
                         cudaFuncAttributeMaxDynamicSharedMemorySize, GEMM_SMEM);

    // 1) alpha
    fro_partial_kernel<<<1024, 256>>>(A, (K_DIM * C_DIM) / 4);
    finalize_alpha_kernel<<<1, 1024>>>(log_scale);

    // 2) operand preparation (fp16, scaled)
    split_transpose_kernel<<<dim3(C_DIM / 32, K_DIM / 32), 256>>>(A, AhT, AlT);
    convert_kernel<<<4096, 256>>>(query, qh, (B_DIM * C_DIM) / 4);

    // 3) G = A^T A (3-term fp16) -> G fp32 + Gh = fp16(16G); triangle+mirror
    mma_gemm_kernel<1, 3><<<dim3(C_DIM / 128, C_DIM / 128), 256, GEMM_SMEM>>>(
        AhT, AlT, AhT, AlT, K_DIM, nullptr, G, Gh, C_DIM, 1, 0.f);

    // 4) P8 = k1*G + k2*(16G @ 16G) -> Ph = fp16(8192*P); triangle+mirror
    mma_gemm_kernel<2, 1><<<dim3(C_DIM / 128, C_DIM / 128), 256, GEMM_SMEM>>>(
        Gh, nullptr, Gh, nullptr, C_DIM, G, nullptr, Ph, C_DIM, 1, 0.f);

    // 5) out = qh @ Ph * 2^-13   (1-term, 4-stage pipeline)
    mma_gemm_kernel<0, 1><<<dim3(C_DIM / 128, B_DIM / 128), 256, GEMM_SMEM>>>(
        qh, nullptr, Ph, nullptr, C_DIM, nullptr, out, nullptr, C_DIM, 0,
        1.0f / 8192.0f);
}

// round 8
// speedup vs baseline: 1.2147x; 1.2147x over previous
#include <cuda_runtime.h>
#include <cuda_fp16.h>
#include <math.h>
#include <stdint.h>

#define K_DIM 4096
#define C_DIM 2048
#define B_DIM 8192

// ---------------------------------------------------------------------------
// Device scratch (no allocation allowed)
// ---------------------------------------------------------------------------
__device__ float g_partial[1024];
__device__ float g_coef[2];   // {k1 = 8192*256*alpha, k2 = 32*(-32640)*alpha^2}

__device__ __half g_AhT[(size_t)C_DIM * K_DIM];  // fp16(64*A^T)  (C x K)
__device__ __half g_AlT[(size_t)C_DIM * K_DIM];  // fp16 residual
__device__ __half g_qh[(size_t)B_DIM * C_DIM];   // fp16(q)
__device__ __half g_ql[(size_t)B_DIM * C_DIM];   // fp16(q - qh)  (subnormals ok)
__device__ float  g_G [(size_t)C_DIM * C_DIM];   // G = A^T A (fp32)
__device__ __half g_Gh[(size_t)C_DIM * C_DIM];   // fp16(16*G)
__device__ __half g_Ph[(size_t)C_DIM * C_DIM];   // fp16(8192*P)

// ---------------------------------------------------------------------------
// Helpers (baseline sm_103 PTX only: cp.async + ldmatrix + mma.sync)
// ---------------------------------------------------------------------------
__device__ __forceinline__ uint32_t smem_to_u32(const void* smem_ptr) {
    uint32_t addr;
    asm("{ .reg .u64 tmp; cvta.to.shared.u64 tmp, %1; cvt.u32.u64 %0, tmp; }"
        : "=r"(addr) : "l"(smem_ptr));
    return addr;
}

__device__ __forceinline__ void cp_async16(uint32_t dst, const void* src) {
    asm volatile("cp.async.cg.shared.global [%0], [%1], 16;"
                 :: "r"(dst), "l"(src));
}
#define CP_COMMIT() asm volatile("cp.async.commit_group;" ::: "memory")
#define CP_WAIT1()  asm volatile("cp.async.wait_group 1;" ::: "memory")
#define CP_WAIT0()  asm volatile("cp.async.wait_group 0;" ::: "memory")

__device__ __forceinline__ void ldsm_x4(uint32_t& r0, uint32_t& r1,
                                        uint32_t& r2, uint32_t& r3,
                                        uint32_t addr) {
    asm volatile("ldmatrix.sync.aligned.m8n8.x4.shared.b16 {%0,%1,%2,%3}, [%4];"
                 : "=r"(r0), "=r"(r1), "=r"(r2), "=r"(r3) : "r"(addr));
}

__device__ __forceinline__ void mma16816(float* c, const uint32_t* a,
                                         const uint32_t* b) {
    asm volatile(
        "mma.sync.aligned.m16n8k16.row.col.f32.f16.f16.f32 "
        "{%0,%1,%2,%3}, {%4,%5,%6,%7}, {%8,%9}, {%0,%1,%2,%3};"
        : "+f"(c[0]), "+f"(c[1]), "+f"(c[2]), "+f"(c[3])
        : "r"(a[0]), "r"(a[1]), "r"(a[2]), "r"(a[3]), "r"(b[0]), "r"(b[1]));
}

__device__ __forceinline__ uint32_t pack_h2(float a, float b) {
    __half2 h = __floats2half2_rn(a, b);
    return *reinterpret_cast<uint32_t*>(&h);
}

// ---------------------------------------------------------------------------
// ||A||_F^2 + alpha
// ---------------------------------------------------------------------------
__global__ void fro_partial_kernel(const float* __restrict__ A, int n4) {
    const float4* A4 = (const float4*)A;
    float s = 0.f;
    for (int i = blockIdx.x * blockDim.x + threadIdx.x; i < n4;
         i += gridDim.x * blockDim.x) {
        float4 v = A4[i];
        s += v.x * v.x + v.y * v.y + v.z * v.z + v.w * v.w;
    }
    __shared__ float sh[256];
    int t = threadIdx.x;
    sh[t] = s;
    __syncthreads();
    for (int o = 128; o > 0; o >>= 1) {
        if (t < o) sh[t] += sh[t + o];
        __syncthreads();
    }
    if (t == 0) g_partial[blockIdx.x] = sh[0];
}

__global__ void finalize_alpha_kernel(const float* __restrict__ log_scale) {
    __shared__ float sh[1024];
    int t = threadIdx.x;
    sh[t] = g_partial[t];
    __syncthreads();
    for (int o = 512; o > 0; o >>= 1) {
        if (t < o) sh[t] += sh[t + o];
        __syncthreads();
    }
    if (t == 0) {
        float fro = sh[0];
        float a = fminf(expf(log_scale[0]), 5e-4f) / (fro + 1e-8f);
        g_coef[0] = 2097152.0f * a;          // 8192*256*alpha
        g_coef[1] = -1044480.0f * a * a;     // 32*(-32640)*alpha^2
    }
}

// ---------------------------------------------------------------------------
// Operand prep: A (K x C fp32) -> A^T hi/lo fp16 (scaled by 64), C x K
// ---------------------------------------------------------------------------
__global__ __launch_bounds__(256) void split_transpose_kernel(
    const float* __restrict__ A, __half* __restrict__ hiT,
    __half* __restrict__ loT) {
    __shared__ float tile[32][33];
    int tx = threadIdx.x & 31, ty = threadIdx.x >> 5;
    int c0 = blockIdx.x * 32;
    int k0 = blockIdx.y * 32;
#pragma unroll
    for (int i = 0; i < 4; i++) {
        int r = ty + i * 8;
        tile[r][tx] = A[(size_t)(k0 + r) * C_DIM + c0 + tx];
    }
    __syncthreads();
#pragma unroll
    for (int i = 0; i < 4; i++) {
        int p = ty + i * 8;
        float v = tile[tx][p] * 64.0f;
        size_t o = (size_t)(c0 + p) * K_DIM + k0 + tx;
        __half h = __float2half_rn(v);
        hiT[o] = h;
        loT[o] = __float2half_rn(v - __half2float(h));  // subnormal-safe
    }
}

// q -> qh + ql (fp16; residual lives in low-normals/subnormals)
__global__ __launch_bounds__(256) void split_kernel(
    const float* __restrict__ X, __half* __restrict__ hi,
    __half* __restrict__ lo, int n4) {
    const float4* X4 = (const float4*)X;
    uint2* H = (uint2*)hi;
    uint2* L = (uint2*)lo;
    for (int i = blockIdx.x * blockDim.x + threadIdx.x; i < n4;
         i += gridDim.x * blockDim.x) {
        float4 v = X4[i];
        __half h0 = __float2half_rn(v.x), h1 = __float2half_rn(v.y);
        __half h2 = __float2half_rn(v.z), h3 = __float2half_rn(v.w);
        uint2 h, l;
        { __half2 t = __halves2half2(h0, h1); h.x = *reinterpret_cast<uint32_t*>(&t); }
        { __half2 t = __halves2half2(h2, h3); h.y = *reinterpret_cast<uint32_t*>(&t); }
        l.x = pack_h2(v.x - __half2float(h0), v.y - __half2float(h1));
        l.y = pack_h2(v.z - __half2float(h2), v.w - __half2float(h3));
        H[i] = h;
        L[i] = l;
    }
}

// ---------------------------------------------------------------------------
// Unified mma.sync fp16 GEMM, K-major operands, acc fp32.
//   NT==3: acc = Ah.Bh^T + Al.Bh^T + Ah.Bl^T  (2-stage, 2 syncs/kt)
//   NT==2: acc = (Ah+Al).Bh^T                 (3-stage, 1 sync/kt, batched)
//   NT==1: acc = Ah.Bh^T                      (3-stage, 1 sync/kt, batched)
// CTA 128x128, 8 warps (2x4), warp tile 64x32, K-tile 32, ROWB=80 pad.
// EPI 0: Fout = s_f * acc
// EPI 1: Fout = acc/4096 (=G); Hout = fp16(acc/256) (=16G)    [+mirror if sym]
// EPI 2: Hout = fp16(k1*Gin + k2*acc)  (=8192*P)              [+mirror if sym]
// ---------------------------------------------------------------------------
#define KT 32
#define ROWB 80
#define TILE_BYTES (128 * ROWB)          // 10240
#define GEMM_SMEM_MAX 92160              // NT2: 3 stages x 3 tiles

template <int EPI, int NT>
__global__ void __launch_bounds__(256, 2) mma_gemm_kernel(
    const __half* __restrict__ Ah, const __half* __restrict__ Al,
    const __half* __restrict__ Bh, const __half* __restrict__ Bl,
    int K,
    const float* __restrict__ Gin, float* __restrict__ Fout,
    __half* __restrict__ Hout,
    int N, int sym, float s_f) {
    if (sym && (int)blockIdx.x > (int)blockIdx.y) return;

    extern __shared__ char smem[];
    const uint32_t smem_u = smem_to_u32(smem);
    const int tid = threadIdx.x;
    const int lane = tid & 31;
    const int warp = tid >> 5;
    const int wm = warp & 1;
    const int wn = warp >> 1;
    const int bm = blockIdx.y * 128;
    const int bn = blockIdx.x * 128;
    const int ktpt = K / KT;

    const int NSTG = (NT == 3) ? 2 : 3;
    const int STAGEB = (NT + 1) * TILE_BYTES;

    float acc[4][4][4];
#pragma unroll
    for (int mi = 0; mi < 4; mi++)
#pragma unroll
        for (int ni = 0; ni < 4; ni++)
#pragma unroll
            for (int c = 0; c < 4; c++) acc[mi][ni][c] = 0.f;

    const int cr = tid >> 2;       // row 0..63 (two passes -> 0..127)
    const int cc = tid & 3;        // 16B chunk

    auto issue = [&](int kt) {
        int k0 = kt * KT;
        uint32_t s = smem_u + (kt % NSTG) * STAGEB;
#pragma unroll
        for (int i = 0; i < 2; i++) {
            int r = cr + i * 64;
            cp_async16(s + r * ROWB + cc * 16,
                       Ah + (size_t)(bm + r) * K + k0 + cc * 8);
        }
#pragma unroll
        for (int i = 0; i < 2; i++) {
            int r = cr + i * 64;
            cp_async16(s + TILE_BYTES + r * ROWB + cc * 16,
                       Bh + (size_t)(bn + r) * K + k0 + cc * 8);
        }
        if (NT >= 2) {
#pragma unroll
            for (int i = 0; i < 2; i++) {
                int r = cr + i * 64;
                cp_async16(s + 2 * TILE_BYTES + r * ROWB + cc * 16,
                           Al + (size_t)(bm + r) * K + k0 + cc * 8);
            }
        }
        if (NT == 3) {
#pragma unroll
            for (int i = 0; i < 2; i++) {
                int r = cr + i * 64;
                cp_async16(s + 3 * TILE_BYTES + r * ROWB + cc * 16,
                           Bl + (size_t)(bn + r) * K + k0 + cc * 8);
            }
        }
        CP_COMMIT();
    };

    // prologue: 2 stages in flight
    issue(0);
    issue(1);

    // ldmatrix lane addressing
    const int arow = lane & 15;
    const int akb = (lane >> 4) * 16;
    const int brow = (lane & 7) + ((lane >> 4) << 3);
    const int bkb = ((lane >> 3) & 1) * 16;

    for (int kt = 0; kt < ktpt; kt++) {
        CP_WAIT1();          // stage kt landed (<=1 pending after)
        __syncthreads();     // cross-thread visibility + overwrite safety
        uint32_t s0 = smem_u + (kt % NSTG) * STAGEB;

        if (NT != 3) {
            // 3-stage: issue now (overwrites stage consumed at kt-1; safe
            // because every warp passed the barrier after finishing kt-1)
            int nx = kt + 2;
            if (nx < ktpt) issue(nx);
            else CP_COMMIT();
        }

#pragma unroll
        for (int ks = 0; ks < 2; ks++) {
            uint32_t a[4][4];
            uint32_t b[4][2];
#pragma unroll
            for (int mi = 0; mi < 4; mi++)
                ldsm_x4(a[mi][0], a[mi][1], a[mi][2], a[mi][3],
                        s0 + (uint32_t)(wm * 64 + mi * 16 + arow) * ROWB +
                            ks * 32 + akb);
#pragma unroll
            for (int nb = 0; nb < 2; nb++)
                ldsm_x4(b[2 * nb][0], b[2 * nb][1], b[2 * nb + 1][0],
                        b[2 * nb + 1][1],
                        s0 + TILE_BYTES +
                            (uint32_t)(wn * 32 + nb * 16 + brow) * ROWB +
                            ks * 32 + bkb);
            if (NT == 1) {
#pragma unroll
                for (int mi = 0; mi < 4; mi++)
#pragma unroll
                    for (int ni = 0; ni < 4; ni++)
                        mma16816(acc[mi][ni], a[mi], b[ni]);
            } else if (NT == 2) {
                // batch all loads first, then 32 MMAs
                uint32_t al[4][4];
#pragma unroll
                for (int mi = 0; mi < 4; mi++)
                    ldsm_x4(al[mi][0], al[mi][1], al[mi][2], al[mi][3],
                            s0 + 2 * TILE_BYTES +
                                (uint32_t)(wm * 64 + mi * 16 + arow) * ROWB +
                                ks * 32 + akb);
#pragma unroll
                for (int mi = 0; mi < 4; mi++)
#pragma unroll
                    for (int ni = 0; ni < 4; ni++)
                        mma16816(acc[mi][ni], a[mi], b[ni]);
#pragma unroll
                for (int mi = 0; mi < 4; mi++)
#pragma unroll
                    for (int ni = 0; ni < 4; ni++)
                        mma16816(acc[mi][ni], al[mi], b[ni]);
            } else {  // NT == 3
#pragma unroll
                for (int mi = 0; mi < 4; mi++)
#pragma unroll
                    for (int ni = 0; ni < 4; ni++)
                        mma16816(acc[mi][ni], a[mi], b[ni]);
                uint32_t al[4][4];
#pragma unroll
                for (int mi = 0; mi < 4; mi++)
                    ldsm_x4(al[mi][0], al[mi][1], al[mi][2], al[mi][3],
                            s0 + 2 * TILE_BYTES +
                                (uint32_t)(wm * 64 + mi * 16 + arow) * ROWB +
                                ks * 32 + akb);
#pragma unroll
                for (int mi = 0; mi < 4; mi++)
#pragma unroll
                    for (int ni = 0; ni < 4; ni++)
                        mma16816(acc[mi][ni], al[mi], b[ni]);
                uint32_t bl[4][2];
#pragma unroll
                for (int nb = 0; nb < 2; nb++)
                    ldsm_x4(bl[2 * nb][0], bl[2 * nb][1], bl[2 * nb + 1][0],
                            bl[2 * nb + 1][1],
                            s0 + 3 * TILE_BYTES +
                                (uint32_t)(wn * 32 + nb * 16 + brow) * ROWB +
                                ks * 32 + bkb);
#pragma unroll
                for (int mi = 0; mi < 4; mi++)
#pragma unroll
                    for (int ni = 0; ni < 4; ni++)
                        mma16816(acc[mi][ni], a[mi], bl[ni]);
            }
        }

        if (NT == 3) {
            // 2-stage: must finish reading before refilling this slot's pair
            __syncthreads();
            int nx = kt + 2;
            if (nx < ktpt) issue(nx);
            else CP_COMMIT();
        }
    }
    CP_WAIT0();

    // ---------------- epilogue ----------------
    const int g = lane >> 2;
    const int tc = lane & 3;
    const int mirror = sym && ((int)blockIdx.x != (int)blockIdx.y);
    float k1 = 0.f, k2 = 0.f;
    if (EPI == 2) { k1 = g_coef[0]; k2 = g_coef[1]; }

#pragma unroll
    for (int mi = 0; mi < 4; mi++) {
#pragma unroll
        for (int ni = 0; ni < 4; ni++) {
#pragma unroll
            for (int half = 0; half < 2; half++) {
                int row = bm + wm * 64 + mi * 16 + g + half * 8;
                int col = bn + wn * 32 + ni * 8 + tc * 2;
                float a0 = acc[mi][ni][half * 2 + 0];
                float a1 = acc[mi][ni][half * 2 + 1];
                size_t off = (size_t)row * N + col;
                if (EPI == 0) {
                    *(float2*)(Fout + off) = make_float2(s_f * a0, s_f * a1);
                } else if (EPI == 1) {
                    float v0 = a0 * (1.0f / 4096.0f);
                    float v1 = a1 * (1.0f / 4096.0f);
                    *(float2*)(Fout + off) = make_float2(v0, v1);
                    uint32_t H = pack_h2(a0 * (1.0f / 256.0f),
                                         a1 * (1.0f / 256.0f));
                    *(uint32_t*)(Hout + off) = H;
                    if (mirror) {
                        Fout[(size_t)col * N + row] = v0;
                        Fout[(size_t)(col + 1) * N + row] = v1;
                        *(unsigned short*)(Hout + (size_t)col * N + row) =
                            (unsigned short)(H & 0xffff);
                        *(unsigned short*)(Hout + (size_t)(col + 1) * N + row) =
                            (unsigned short)(H >> 16);
                    }
                } else {  // EPI == 2
                    float2 gv = *(const float2*)(Gin + off);
                    float v0 = k1 * gv.x + k2 * a0;
                    float v1 = k1 * gv.y + k2 * a1;
                    uint32_t H = pack_h2(v0, v1);
                    *(uint32_t*)(Hout + off) = H;
                    if (mirror) {
                        *(unsigned short*)(Hout + (size_t)col * N + row) =
                            (unsigned short)(H & 0xffff);
                        *(unsigned short*)(Hout + (size_t)(col + 1) * N + row) =
                            (unsigned short)(H >> 16);
                    }
                }
            }
        }
    }
}

// ---------------------------------------------------------------------------
// Launch: retrieved = query @ (c1*G + c2*G^2), G = A^T A  (G, P symmetric)
// ---------------------------------------------------------------------------
extern "C" void kernel_launch(void* const* d_in, const int* in_sizes, int n_in,
                              void* d_out, int out_size) {
    const float* query = (const float*)d_in[0];      // (B, C)
    const float* A = (const float*)d_in[1];          // (K, C)
    const float* log_scale = (const float*)d_in[2];  // scalar
    float* out = (float*)d_out;                      // (B, C)

    __half *AhT, *AlT, *qh, *ql, *Gh, *Ph;
    float* G;
    cudaGetSymbolAddress((void**)&AhT, g_AhT);
    cudaGetSymbolAddress((void**)&AlT, g_AlT);
    cudaGetSymbolAddress((void**)&qh, g_qh);
    cudaGetSymbolAddress((void**)&ql, g_ql);
    cudaGetSymbolAddress((void**)&G, g_G);
    cudaGetSymbolAddress((void**)&Gh, g_Gh);
    cudaGetSymbolAddress((void**)&Ph, g_Ph);

    cudaFuncSetAttribute(mma_gemm_kernel<0, 2>,
                         cudaFuncAttributeMaxDynamicSharedMemorySize,
                         GEMM_SMEM_MAX);
    cudaFuncSetAttribute(mma_gemm_kernel<1, 3>,
                         cudaFuncAttributeMaxDynamicSharedMemorySize,
                         GEMM_SMEM_MAX);
    cudaFuncSetAttribute(mma_gemm_kernel<2, 1>,
                         cudaFuncAttributeMaxDynamicSharedMemorySize,
                         GEMM_SMEM_MAX);

    // 1) alpha
    fro_partial_kernel<<<1024, 256>>>(A, (K_DIM * C_DIM) / 4);
    finalize_alpha_kernel<<<1, 1024>>>(log_scale);

    // 2) operand preparation (fp16, scaled)
    split_transpose_kernel<<<dim3(C_DIM / 32, K_DIM / 32), 256>>>(A, AhT, AlT);
    split_kernel<<<4096, 256>>>(query, qh, ql, (B_DIM * C_DIM) / 4);

    // 3) G = A^T A (3-term, 2-stage) -> G fp32 + Gh = fp16(16G); tri+mirror
    mma_gemm_kernel<1, 3><<<dim3(C_DIM / 128, C_DIM / 128), 256,
                            2 * 4 * TILE_BYTES>>>(
        AhT, AlT, AhT, AlT, K_DIM, nullptr, G, Gh, C_DIM, 1, 0.f);

    // 4) P8 = k1*G + k2*(16G @ 16G) (1-term, 3-stage) -> Ph; tri+mirror
    mma_gemm_kernel<2, 1><<<dim3(C_DIM / 128, C_DIM / 128), 256,
                            3 * 2 * TILE_BYTES>>>(
        Gh, nullptr, Gh, nullptr, C_DIM, G, nullptr, Ph, C_DIM, 1, 0.f);

    // 5) out = (qh + ql) @ Ph * 2^-13  (2-term, 3-stage, shared B operand)
    mma_gemm_kernel<0, 2><<<dim3(C_DIM / 128, B_DIM / 128), 256,
                            3 * 3 * TILE_BYTES>>>(
        qh, ql, Ph, nullptr, C_DIM, nullptr, out, nullptr, C_DIM, 0,
        1.0f / 8192.0f);
}